// round 4
// baseline (speedup 1.0000x reference)
#include <cuda_runtime.h>
#include <cstdint>

#define BATCH 16
#define CH    256
#define SEQ   2048
#define HID   256
#define G3    768
#define M_ROWS (BATCH*SEQ)

typedef unsigned long long ull;

__device__ __forceinline__ ull pack2(float x, float y) {
    ull r; asm("mov.b64 %0,{%1,%2};" : "=l"(r) : "f"(x), "f"(y)); return r;
}
__device__ __forceinline__ void unpack2(ull v, float& x, float& y) {
    asm("mov.b64 {%0,%1},%2;" : "=f"(x), "=f"(y) : "l"(v));
}
__device__ __forceinline__ ull fma2(ull a, ull b, ull c) {
    ull d; asm("fma.rn.f32x2 %0,%1,%2,%3;" : "=l"(d) : "l"(a), "l"(b), "l"(c)); return d;
}
__device__ __forceinline__ float fsig(float x) {
    return __fdividef(1.f, 1.f + __expf(-x));
}
__device__ __forceinline__ float ftanh(float x) {
    float t = __expf(-2.f * fabsf(x));
    return copysignf(__fdividef(1.f - t, 1.f + t), x);
}

__device__ float g_gi  [(size_t)2 * BATCH * SEQ * G3];
__device__ float g_bufA[(size_t)BATCH * SEQ * 2 * HID];
__device__ float g_bufB[(size_t)BATCH * SEQ * 2 * HID];
__device__ float g_bufC[(size_t)BATCH * SEQ * HID];

// ----------------------------- transpose -----------------------------------
__global__ void transpose_k(const float* __restrict__ src, float* __restrict__ dst,
                            int D1, int D2)
{
    __shared__ float tile[32][33];
    const int b  = blockIdx.z;
    const int j0 = blockIdx.x * 32;
    const int i0 = blockIdx.y * 32;
    const float* s = src + (size_t)b * D1 * D2;
    float*       d = dst + (size_t)b * D1 * D2;
    #pragma unroll
    for (int r = 0; r < 32; r += 8)
        tile[threadIdx.y + r][threadIdx.x] =
            s[(size_t)(i0 + threadIdx.y + r) * D2 + j0 + threadIdx.x];
    __syncthreads();
    #pragma unroll
    for (int r = 0; r < 32; r += 8)
        d[(size_t)(j0 + threadIdx.y + r) * D1 + i0 + threadIdx.x] =
            tile[threadIdx.x][threadIdx.y + r];
}

// ----------------------------- SGEMM (double-buffered) ---------------------
__global__ void __launch_bounds__(256, 2)
gemm_kernel(const float* __restrict__ A, const float* __restrict__ Bw,
            const float* __restrict__ bias, float* __restrict__ C,
            int M, int N, int K, int relu)
{
    __shared__ float As[2][16][128];
    __shared__ float Bs[2][16][128];
    const int tid = threadIdx.x;
    const int tx = tid & 15, ty = tid >> 4;
    const float* Ab = A  + (size_t)blockIdx.y * 128 * K;
    const float* Bb = Bw + (size_t)blockIdx.x * 128 * K;
    const int lrow = tid >> 1;
    const int lq   = (tid & 1) * 2;   // k offset lq*4 in {0,8}

    ull c2[8][4];
    #pragma unroll
    for (int i = 0; i < 8; i++)
        #pragma unroll
        for (int j = 0; j < 4; j++) c2[i][j] = 0ull;

    float4 ra0, ra1, rb0, rb1;
    {
        const float* ap = &Ab[(size_t)lrow * K + lq * 4];
        const float* bp = &Bb[(size_t)lrow * K + lq * 4];
        ra0 = *(const float4*)ap; ra1 = *(const float4*)(ap + 4);
        rb0 = *(const float4*)bp; rb1 = *(const float4*)(bp + 4);
    }
    {
        const int q = lq * 4;
        As[0][q+0][lrow]=ra0.x; As[0][q+1][lrow]=ra0.y; As[0][q+2][lrow]=ra0.z; As[0][q+3][lrow]=ra0.w;
        As[0][q+4][lrow]=ra1.x; As[0][q+5][lrow]=ra1.y; As[0][q+6][lrow]=ra1.z; As[0][q+7][lrow]=ra1.w;
        Bs[0][q+0][lrow]=rb0.x; Bs[0][q+1][lrow]=rb0.y; Bs[0][q+2][lrow]=rb0.z; Bs[0][q+3][lrow]=rb0.w;
        Bs[0][q+4][lrow]=rb1.x; Bs[0][q+5][lrow]=rb1.y; Bs[0][q+6][lrow]=rb1.z; Bs[0][q+7][lrow]=rb1.w;
    }
    __syncthreads();

    const int ktiles = K >> 4;
    int buf = 0;
    for (int it = 0; it < ktiles; it++) {
        const int more = (it + 1 < ktiles);
        if (more) {
            const int kt = (it + 1) * 16;
            const float* ap = &Ab[(size_t)lrow * K + kt + lq * 4];
            const float* bp = &Bb[(size_t)lrow * K + kt + lq * 4];
            ra0 = *(const float4*)ap; ra1 = *(const float4*)(ap + 4);
            rb0 = *(const float4*)bp; rb1 = *(const float4*)(bp + 4);
        }
        #pragma unroll
        for (int k = 0; k < 16; k++) {
            float4 a0 = *(const float4*)&As[buf][k][ty * 8];
            float4 a1 = *(const float4*)&As[buf][k][ty * 8 + 4];
            float4 b0 = *(const float4*)&Bs[buf][k][tx * 8];
            float4 b1 = *(const float4*)&Bs[buf][k][tx * 8 + 4];
            ull bp4[4] = { pack2(b0.x, b0.y), pack2(b0.z, b0.w),
                           pack2(b1.x, b1.y), pack2(b1.z, b1.w) };
            float av[8] = { a0.x, a0.y, a0.z, a0.w, a1.x, a1.y, a1.z, a1.w };
            #pragma unroll
            for (int i = 0; i < 8; i++) {
                ull as = pack2(av[i], av[i]);
                #pragma unroll
                for (int j = 0; j < 4; j++) c2[i][j] = fma2(as, bp4[j], c2[i][j]);
            }
        }
        if (more) {
            const int nb = buf ^ 1;
            const int q = lq * 4;
            As[nb][q+0][lrow]=ra0.x; As[nb][q+1][lrow]=ra0.y; As[nb][q+2][lrow]=ra0.z; As[nb][q+3][lrow]=ra0.w;
            As[nb][q+4][lrow]=ra1.x; As[nb][q+5][lrow]=ra1.y; As[nb][q+6][lrow]=ra1.z; As[nb][q+7][lrow]=ra1.w;
            Bs[nb][q+0][lrow]=rb0.x; Bs[nb][q+1][lrow]=rb0.y; Bs[nb][q+2][lrow]=rb0.z; Bs[nb][q+3][lrow]=rb0.w;
            Bs[nb][q+4][lrow]=rb1.x; Bs[nb][q+5][lrow]=rb1.y; Bs[nb][q+6][lrow]=rb1.z; Bs[nb][q+7][lrow]=rb1.w;
            __syncthreads();
            buf = nb;
        }
    }

    const int n0 = blockIdx.x * 128 + tx * 8;
    float bv[8];
    #pragma unroll
    for (int j = 0; j < 8; j++) bv[j] = bias[n0 + j];
    #pragma unroll
    for (int i = 0; i < 8; i++) {
        float o[8];
        #pragma unroll
        for (int j = 0; j < 4; j++) unpack2(c2[i][j], o[2*j], o[2*j+1]);
        #pragma unroll
        for (int j = 0; j < 8; j++) {
            o[j] += bv[j];
            if (relu) o[j] = fmaxf(o[j], 0.f);
        }
        float* cp = &C[((size_t)blockIdx.y * 128 + ty * 8 + i) * N + n0];
        *(float4*)cp       = make_float4(o[0], o[1], o[2], o[3]);
        *(float4*)(cp + 4) = make_float4(o[4], o[5], o[6], o[7]);
    }
}

// ----------------------------- GRU scan (mbarrier sync) --------------------
#define SPLIT 4
#define STH   384

__device__ __forceinline__ void mbar_wait(uint32_t addr, uint32_t parity) {
    asm volatile(
        "{\n\t.reg .pred P;\n\t"
        "LW_%=:\n\t"
        "mbarrier.try_wait.parity.acquire.cluster.shared::cta.b64 P, [%0], %1, 0x989680;\n\t"
        "@!P bra LW_%=;\n\t}"
        :: "r"(addr), "r"(parity) : "memory");
}

__global__ void __launch_bounds__(STH, 1) __cluster_dims__(SPLIT, 1, 1)
scan_kernel(const float* __restrict__ gi,
            const float* __restrict__ whh_f, const float* __restrict__ bhh_f,
            const float* __restrict__ whh_b, const float* __restrict__ bhh_b,
            float* __restrict__ out)
{
    const int ci    = blockIdx.x;
    const int chain = blockIdx.y;
    const int b     = chain & (BATCH - 1);
    const int dir   = chain >> 4;
    const float* whh = dir ? whh_b : whh_f;
    const float* bhh = dir ? bhh_b : bhh_f;
    const float* giB = gi + ((size_t)dir * BATCH + b) * (size_t)SEQ * G3;
    float* outB = out + (size_t)b * SEQ * (2 * HID) + dir * HID;

    const int tid  = threadIdx.x;
    const int g    = tid / 192;          // k half
    const int o    = tid % 192;
    const int gate = o >> 6;
    const int jl   = o & 63;
    const int row  = gate * HID + ci * 64 + jl;
    const int gu   = ci * 64 + jl;       // for tid<64: own unit

    __shared__ __align__(16) float hbuf[2][HID];
    __shared__ float part[STH];
    __shared__ __align__(8) ull mbar[2];

    ull wreg[64];
    {
        const ull* wp = (const ull*)(whh + (size_t)row * HID + g * 128);
        #pragma unroll
        for (int i = 0; i < 64; i++) wreg[i] = wp[i];
    }
    const float bias = (g == 0) ? bhh[row] : 0.f;

    uint32_t hb0, mb0;
    asm("{ .reg .u64 t; cvta.to.shared.u64 t, %1; cvt.u32.u64 %0, t; }"
        : "=r"(hb0) : "l"(&hbuf[0][0]));
    asm("{ .reg .u64 t; cvta.to.shared.u64 t, %1; cvt.u32.u64 %0, t; }"
        : "=r"(mb0) : "l"(&mbar[0]));

    if (tid == 0) {
        asm volatile("mbarrier.init.shared.b64 [%0], 256;" :: "r"(mb0)     : "memory");
        asm volatile("mbarrier.init.shared.b64 [%0], 256;" :: "r"(mb0 + 8) : "memory");
    }
    for (int i = tid; i < 2 * HID; i += STH) (&hbuf[0][0])[i] = 0.f;
    __syncthreads();
    asm volatile("barrier.cluster.arrive.aligned;" ::: "memory");
    asm volatile("barrier.cluster.wait.aligned;"   ::: "memory");

    float hreg = 0.f;
    float p_r = 0.f, p_z = 0.f, p_n = 0.f;
    if (tid < 64) {
        const float* gp = giB + (size_t)(dir ? SEQ - 1 : 0) * G3 + gu;
        p_r = __ldg(gp); p_z = __ldg(gp + HID); p_n = __ldg(gp + 2 * HID);
    }

    for (int s = 0; s < SEQ; s++) {
        const int t = dir ? (SEQ - 1 - s) : s;
        const int p = s & 1;
        if (s > 0) mbar_wait(mb0 + p * 8, ((s - 1) >> 1) & 1);

        const float gi_r = p_r, gi_z = p_z, gi_n = p_n;
        if (tid < 64 && s + 1 < SEQ) {
            const int tn = dir ? (SEQ - 2 - s) : (s + 1);
            const float* gp = giB + (size_t)tn * G3 + gu;
            p_r = __ldg(gp); p_z = __ldg(gp + HID); p_n = __ldg(gp + 2 * HID);
        }

        // 128-long dot over this thread's k half (LDS.128 as 64-bit pairs)
        ull acc0 = pack2(bias, 0.f);
        ull acc1 = 0ull;
        const ulonglong2* h2 = (const ulonglong2*)&hbuf[p][g * 128];
        #pragma unroll
        for (int kk = 0; kk < 32; kk++) {
            ulonglong2 hv = h2[kk];
            acc0 = fma2(wreg[2*kk],     hv.x, acc0);
            acc1 = fma2(wreg[2*kk + 1], hv.y, acc1);
        }
        float aa, bb, cc, dd;
        unpack2(acc0, aa, bb); unpack2(acc1, cc, dd);
        part[tid] = (aa + cc) + (bb + dd);
        __syncthreads();

        if (tid < 64) {
            const float gh_r = part[tid]       + part[192 + tid];
            const float gh_z = part[64 + tid]  + part[256 + tid];
            const float gh_n = part[128 + tid] + part[320 + tid];
            const float r = fsig(gi_r + gh_r);
            const float z = fsig(gi_z + gh_z);
            const float n = ftanh(gi_n + r * gh_n);
            hreg = n + z * (hreg - n);
            outB[(size_t)t * (2 * HID) + gu] = hreg;
            if (s + 1 < SEQ) {
                const uint32_t dst = hb0 + (uint32_t)(((p ^ 1) * HID + gu) * 4);
                const uint32_t mdst = mb0 + (uint32_t)((p ^ 1) * 8);
                #pragma unroll
                for (int peer = 0; peer < SPLIT; peer++) {
                    uint32_t ra;
                    asm volatile("mapa.shared::cluster.u32 %0, %1, %2;"
                                 : "=r"(ra) : "r"(dst), "r"(peer));
                    asm volatile("st.shared::cluster.f32 [%0], %1;"
                                 :: "r"(ra), "f"(hreg) : "memory");
                }
                #pragma unroll
                for (int peer = 0; peer < SPLIT; peer++) {
                    uint32_t ra;
                    asm volatile("mapa.shared::cluster.u32 %0, %1, %2;"
                                 : "=r"(ra) : "r"(mdst), "r"(peer));
                    asm volatile("mbarrier.arrive.release.cluster.shared::cluster.b64 _, [%0];"
                                 :: "r"(ra) : "memory");
                }
            }
        }
    }
}

// ----------------------------- sum dirs + LayerNorm ------------------------
__global__ void sum_ln_kernel(const float* __restrict__ in,
                              const float* __restrict__ gw,
                              const float* __restrict__ bw,
                              float* __restrict__ out)
{
    const int lane = threadIdx.x & 31;
    const size_t row = (size_t)blockIdx.x * 8 + (threadIdx.x >> 5);
    const float* r = in + row * 512;
    float v[8]; float s = 0.f, s2 = 0.f;
    #pragma unroll
    for (int i = 0; i < 8; i++) {
        int c = i * 32 + lane;
        v[i] = r[c] + r[256 + c];
        s += v[i]; s2 += v[i] * v[i];
    }
    #pragma unroll
    for (int off = 16; off; off >>= 1) {
        s  += __shfl_xor_sync(~0u, s,  off);
        s2 += __shfl_xor_sync(~0u, s2, off);
    }
    const float mu  = s * (1.f / 256.f);
    const float var = s2 * (1.f / 256.f) - mu * mu;
    const float inv = rsqrtf(var + 1e-5f);
    float* op = out + row * 256;
    #pragma unroll
    for (int i = 0; i < 8; i++) {
        int c = i * 32 + lane;
        op[c] = (v[i] - mu) * inv * gw[c] + bw[c];
    }
}

// ----------------------------- orchestration -------------------------------
extern "C" void kernel_launch(void* const* d_in, const int* in_sizes, int n_in,
                              void* d_out, int out_size)
{
    (void)in_sizes; (void)n_in; (void)out_size;
    const float* x      = (const float*)d_in[0];
    const float* w_ih0f = (const float*)d_in[1];
    const float* w_hh0f = (const float*)d_in[2];
    const float* b_ih0f = (const float*)d_in[3];
    const float* b_hh0f = (const float*)d_in[4];
    const float* w_ih0b = (const float*)d_in[5];
    const float* w_hh0b = (const float*)d_in[6];
    const float* b_ih0b = (const float*)d_in[7];
    const float* b_hh0b = (const float*)d_in[8];
    const float* w_ih1f = (const float*)d_in[9];
    const float* w_hh1f = (const float*)d_in[10];
    const float* b_ih1f = (const float*)d_in[11];
    const float* b_hh1f = (const float*)d_in[12];
    const float* w_ih1b = (const float*)d_in[13];
    const float* w_hh1b = (const float*)d_in[14];
    const float* b_ih1b = (const float*)d_in[15];
    const float* b_hh1b = (const float*)d_in[16];
    const float* ln_g   = (const float*)d_in[17];
    const float* ln_b   = (const float*)d_in[18];
    const float* w1     = (const float*)d_in[19];
    const float* b1     = (const float*)d_in[20];
    const float* w2     = (const float*)d_in[21];
    const float* b2     = (const float*)d_in[22];

    float *gi, *bufA, *bufB, *bufC;
    cudaGetSymbolAddress((void**)&gi,   g_gi);
    cudaGetSymbolAddress((void**)&bufA, g_bufA);
    cudaGetSymbolAddress((void**)&bufB, g_bufB);
    cudaGetSymbolAddress((void**)&bufC, g_bufC);

    const dim3 tb(32, 8);
    const dim3 gemm_grid(G3 / 128, M_ROWS / 128);

    transpose_k<<<dim3(SEQ / 32, CH / 32, BATCH), tb>>>(x, bufC, CH, SEQ);

    gemm_kernel<<<gemm_grid, 256>>>(bufC, w_ih0f, b_ih0f, gi,                       M_ROWS, G3, CH, 0);
    gemm_kernel<<<gemm_grid, 256>>>(bufC, w_ih0b, b_ih0b, gi + (size_t)M_ROWS * G3, M_ROWS, G3, CH, 0);

    scan_kernel<<<dim3(SPLIT, 2 * BATCH), STH>>>(gi, w_hh0f, b_hh0f, w_hh0b, b_hh0b, bufA);

    gemm_kernel<<<gemm_grid, 256>>>(bufA, w_ih1f, b_ih1f, gi,                       M_ROWS, G3, 2 * HID, 0);
    gemm_kernel<<<gemm_grid, 256>>>(bufA, w_ih1b, b_ih1b, gi + (size_t)M_ROWS * G3, M_ROWS, G3, 2 * HID, 0);

    scan_kernel<<<dim3(SPLIT, 2 * BATCH), STH>>>(gi, w_hh1f, b_hh1f, w_hh1b, b_hh1b, bufB);

    sum_ln_kernel<<<M_ROWS / 8, 256>>>(bufB, ln_g, ln_b, bufC);

    gemm_kernel<<<dim3(512 / 128, M_ROWS / 128), 256>>>(bufC, w1, b1, bufA, M_ROWS, 512, 256, 1);
    gemm_kernel<<<dim3(256 / 128, M_ROWS / 128), 256>>>(bufA, w2, b2, gi,   M_ROWS, 256, 512, 0);

    transpose_k<<<dim3(CH / 32, SEQ / 32, BATCH), tb>>>(gi, (float*)d_out, SEQ, CH);
}

// round 5
// speedup vs baseline: 1.0077x; 1.0077x over previous
#include <cuda_runtime.h>
#include <cstdint>

#define BATCH 16
#define CH    256
#define SEQ   2048
#define HID   256
#define G3    768
#define M_ROWS (BATCH*SEQ)

typedef unsigned long long ull;

__device__ __forceinline__ ull pack2(float x, float y) {
    ull r; asm("mov.b64 %0,{%1,%2};" : "=l"(r) : "f"(x), "f"(y)); return r;
}
__device__ __forceinline__ void unpack2(ull v, float& x, float& y) {
    asm("mov.b64 {%0,%1},%2;" : "=f"(x), "=f"(y) : "l"(v));
}
__device__ __forceinline__ ull fma2(ull a, ull b, ull c) {
    ull d; asm("fma.rn.f32x2 %0,%1,%2,%3;" : "=l"(d) : "l"(a), "l"(b), "l"(c)); return d;
}
__device__ __forceinline__ float fsig(float x) {
    return __fdividef(1.f, 1.f + __expf(-x));
}
__device__ __forceinline__ float ftanh(float x) {
    float t = __expf(-2.f * fabsf(x));
    return copysignf(__fdividef(1.f - t, 1.f + t), x);
}

__device__ float g_gi  [(size_t)2 * BATCH * SEQ * G3];
__device__ float g_bufA[(size_t)BATCH * SEQ * 2 * HID];
__device__ float g_bufB[(size_t)BATCH * SEQ * 2 * HID];
__device__ float g_bufC[(size_t)BATCH * SEQ * HID];

// ----------------------------- transpose -----------------------------------
__global__ void transpose_k(const float* __restrict__ src, float* __restrict__ dst,
                            int D1, int D2)
{
    __shared__ float tile[32][33];
    const int b  = blockIdx.z;
    const int j0 = blockIdx.x * 32;
    const int i0 = blockIdx.y * 32;
    const float* s = src + (size_t)b * D1 * D2;
    float*       d = dst + (size_t)b * D1 * D2;
    #pragma unroll
    for (int r = 0; r < 32; r += 8)
        tile[threadIdx.y + r][threadIdx.x] =
            s[(size_t)(i0 + threadIdx.y + r) * D2 + j0 + threadIdx.x];
    __syncthreads();
    #pragma unroll
    for (int r = 0; r < 32; r += 8)
        d[(size_t)(j0 + threadIdx.y + r) * D1 + i0 + threadIdx.x] =
            tile[threadIdx.x][threadIdx.y + r];
}

// ----------------------------- SGEMM (double-buffered) ---------------------
__global__ void __launch_bounds__(256, 2)
gemm_kernel(const float* __restrict__ A, const float* __restrict__ Bw,
            const float* __restrict__ bias, float* __restrict__ C,
            int M, int N, int K, int relu)
{
    __shared__ float As[2][16][128];
    __shared__ float Bs[2][16][128];
    const int tid = threadIdx.x;
    const int tx = tid & 15, ty = tid >> 4;
    const float* Ab = A  + (size_t)blockIdx.y * 128 * K;
    const float* Bb = Bw + (size_t)blockIdx.x * 128 * K;
    const int lrow = tid >> 1;
    const int lq   = (tid & 1) * 2;

    ull c2[8][4];
    #pragma unroll
    for (int i = 0; i < 8; i++)
        #pragma unroll
        for (int j = 0; j < 4; j++) c2[i][j] = 0ull;

    float4 ra0, ra1, rb0, rb1;
    {
        const float* ap = &Ab[(size_t)lrow * K + lq * 4];
        const float* bp = &Bb[(size_t)lrow * K + lq * 4];
        ra0 = *(const float4*)ap; ra1 = *(const float4*)(ap + 4);
        rb0 = *(const float4*)bp; rb1 = *(const float4*)(bp + 4);
    }
    {
        const int q = lq * 4;
        As[0][q+0][lrow]=ra0.x; As[0][q+1][lrow]=ra0.y; As[0][q+2][lrow]=ra0.z; As[0][q+3][lrow]=ra0.w;
        As[0][q+4][lrow]=ra1.x; As[0][q+5][lrow]=ra1.y; As[0][q+6][lrow]=ra1.z; As[0][q+7][lrow]=ra1.w;
        Bs[0][q+0][lrow]=rb0.x; Bs[0][q+1][lrow]=rb0.y; Bs[0][q+2][lrow]=rb0.z; Bs[0][q+3][lrow]=rb0.w;
        Bs[0][q+4][lrow]=rb1.x; Bs[0][q+5][lrow]=rb1.y; Bs[0][q+6][lrow]=rb1.z; Bs[0][q+7][lrow]=rb1.w;
    }
    __syncthreads();

    const int ktiles = K >> 4;
    int buf = 0;
    for (int it = 0; it < ktiles; it++) {
        const int more = (it + 1 < ktiles);
        if (more) {
            const int kt = (it + 1) * 16;
            const float* ap = &Ab[(size_t)lrow * K + kt + lq * 4];
            const float* bp = &Bb[(size_t)lrow * K + kt + lq * 4];
            ra0 = *(const float4*)ap; ra1 = *(const float4*)(ap + 4);
            rb0 = *(const float4*)bp; rb1 = *(const float4*)(bp + 4);
        }
        #pragma unroll
        for (int k = 0; k < 16; k++) {
            float4 a0 = *(const float4*)&As[buf][k][ty * 8];
            float4 a1 = *(const float4*)&As[buf][k][ty * 8 + 4];
            float4 b0 = *(const float4*)&Bs[buf][k][tx * 8];
            float4 b1 = *(const float4*)&Bs[buf][k][tx * 8 + 4];
            ull bp4[4] = { pack2(b0.x, b0.y), pack2(b0.z, b0.w),
                           pack2(b1.x, b1.y), pack2(b1.z, b1.w) };
            float av[8] = { a0.x, a0.y, a0.z, a0.w, a1.x, a1.y, a1.z, a1.w };
            #pragma unroll
            for (int i = 0; i < 8; i++) {
                ull as = pack2(av[i], av[i]);
                #pragma unroll
                for (int j = 0; j < 4; j++) c2[i][j] = fma2(as, bp4[j], c2[i][j]);
            }
        }
        if (more) {
            const int nb = buf ^ 1;
            const int q = lq * 4;
            As[nb][q+0][lrow]=ra0.x; As[nb][q+1][lrow]=ra0.y; As[nb][q+2][lrow]=ra0.z; As[nb][q+3][lrow]=ra0.w;
            As[nb][q+4][lrow]=ra1.x; As[nb][q+5][lrow]=ra1.y; As[nb][q+6][lrow]=ra1.z; As[nb][q+7][lrow]=ra1.w;
            Bs[nb][q+0][lrow]=rb0.x; Bs[nb][q+1][lrow]=rb0.y; Bs[nb][q+2][lrow]=rb0.z; Bs[nb][q+3][lrow]=rb0.w;
            Bs[nb][q+4][lrow]=rb1.x; Bs[nb][q+5][lrow]=rb1.y; Bs[nb][q+6][lrow]=rb1.z; Bs[nb][q+7][lrow]=rb1.w;
            __syncthreads();
            buf = nb;
        }
    }

    const int n0 = blockIdx.x * 128 + tx * 8;
    float bv[8];
    #pragma unroll
    for (int j = 0; j < 8; j++) bv[j] = bias[n0 + j];
    #pragma unroll
    for (int i = 0; i < 8; i++) {
        float o[8];
        #pragma unroll
        for (int j = 0; j < 4; j++) unpack2(c2[i][j], o[2*j], o[2*j+1]);
        #pragma unroll
        for (int j = 0; j < 8; j++) {
            o[j] += bv[j];
            if (relu) o[j] = fmaxf(o[j], 0.f);
        }
        float* cp = &C[((size_t)blockIdx.y * 128 + ty * 8 + i) * N + n0];
        *(float4*)cp       = make_float4(o[0], o[1], o[2], o[3]);
        *(float4*)(cp + 4) = make_float4(o[4], o[5], o[6], o[7]);
    }
}

// ----------------------------- GRU scan (quad layout, barrier.cluster) -----
// Cluster of 4 CTAs per (batch,dir) chain; CTA ci owns units [ci*64, ci*64+64).
// Thread = (unit j = tid>>2, k-quarter q = tid&3). Each thread holds all 3
// gate rows x 64 k of w_hh in 96 f32x2 regs. Dot reads h as ulonglong2
// (no packs). Cross-quarter reduce = 2x SHFL.BFLY inside the quad. Lane q==0
// does gate math and broadcasts h_new to all 4 CTAs' next-parity buffer.
#define SPLIT 4
#define STH   256

__global__ void __launch_bounds__(STH, 1) __cluster_dims__(SPLIT, 1, 1)
scan_kernel(const float* __restrict__ gi,
            const float* __restrict__ whh_f, const float* __restrict__ bhh_f,
            const float* __restrict__ whh_b, const float* __restrict__ bhh_b,
            float* __restrict__ out)
{
    const int ci    = blockIdx.x;
    const int chain = blockIdx.y;
    const int b     = chain & (BATCH - 1);
    const int dir   = chain >> 4;
    const float* whh = dir ? whh_b : whh_f;
    const float* bhh = dir ? bhh_b : bhh_f;
    const float* giB = gi + ((size_t)dir * BATCH + b) * (size_t)SEQ * G3;
    float* outB = out + (size_t)b * SEQ * (2 * HID) + dir * HID;

    const int tid = threadIdx.x;
    const int j   = tid >> 2;        // unit within slice
    const int q   = tid & 3;         // k quarter
    const int gu  = ci * 64 + j;     // global hidden unit
    const int is0 = (q == 0);

    __shared__ __align__(16) float hbuf[2][HID];

    // 3 gate rows x 64-k quarter into registers
    ull wr[32], wz[32], wn[32];
    {
        const ull* p0 = (const ull*)(whh + (size_t)(        gu) * HID + q * 64);
        const ull* p1 = (const ull*)(whh + (size_t)(HID   + gu) * HID + q * 64);
        const ull* p2 = (const ull*)(whh + (size_t)(2*HID + gu) * HID + q * 64);
        #pragma unroll
        for (int i = 0; i < 32; i++) { wr[i] = p0[i]; wz[i] = p1[i]; wn[i] = p2[i]; }
    }
    const float br = bhh[gu], bz = bhh[HID + gu], bn = bhh[2 * HID + gu];

    uint32_t hb0;
    asm("{ .reg .u64 t; cvta.to.shared.u64 t, %1; cvt.u32.u64 %0, t; }"
        : "=r"(hb0) : "l"(&hbuf[0][0]));

    for (int i = tid; i < 2 * HID; i += STH) (&hbuf[0][0])[i] = 0.f;
    __syncthreads();
    asm volatile("barrier.cluster.arrive.aligned;" ::: "memory");
    asm volatile("barrier.cluster.wait.aligned;"   ::: "memory");

    float hreg = 0.f;
    float p_r = 0.f, p_z = 0.f, p_n = 0.f;
    if (is0) {
        const float* gp = giB + (size_t)(dir ? SEQ - 1 : 0) * G3 + gu;
        p_r = __ldg(gp); p_z = __ldg(gp + HID); p_n = __ldg(gp + 2 * HID);
    }

    for (int s = 0; s < SEQ; s++) {
        const int t = dir ? (SEQ - 1 - s) : s;
        const int p = s & 1;
        const float gi_r = p_r, gi_z = p_z, gi_n = p_n;
        if (is0 && s + 1 < SEQ) {
            const int tn = dir ? (SEQ - 2 - s) : (s + 1);
            const float* gp = giB + (size_t)tn * G3 + gu;
            p_r = __ldg(gp); p_z = __ldg(gp + HID); p_n = __ldg(gp + 2 * HID);
        }

        // 64-long k-quarter dot for all 3 gates (h via LDS.128, no packs)
        ull ar0 = 0ull, ar1 = 0ull, az0 = 0ull, az1 = 0ull, an0 = 0ull, an1 = 0ull;
        const ulonglong2* h2 = (const ulonglong2*)&hbuf[p][q * 64];
        #pragma unroll
        for (int kk = 0; kk < 16; kk++) {
            ulonglong2 hv = h2[kk];
            ar0 = fma2(wr[2*kk], hv.x, ar0); ar1 = fma2(wr[2*kk+1], hv.y, ar1);
            az0 = fma2(wz[2*kk], hv.x, az0); az1 = fma2(wz[2*kk+1], hv.y, az1);
            an0 = fma2(wn[2*kk], hv.x, an0); an1 = fma2(wn[2*kk+1], hv.y, an1);
        }
        float x0, x1, y0, y1;
        unpack2(ar0, x0, x1); unpack2(ar1, y0, y1); float ghr = (x0 + y0) + (x1 + y1);
        unpack2(az0, x0, x1); unpack2(az1, y0, y1); float ghz = (x0 + y0) + (x1 + y1);
        unpack2(an0, x0, x1); unpack2(an1, y0, y1); float ghn = (x0 + y0) + (x1 + y1);
        ghr += __shfl_xor_sync(~0u, ghr, 1); ghr += __shfl_xor_sync(~0u, ghr, 2);
        ghz += __shfl_xor_sync(~0u, ghz, 1); ghz += __shfl_xor_sync(~0u, ghz, 2);
        ghn += __shfl_xor_sync(~0u, ghn, 1); ghn += __shfl_xor_sync(~0u, ghn, 2);

        if (is0) {
            const float r = fsig(gi_r + ghr + br);
            const float z = fsig(gi_z + ghz + bz);
            const float n = ftanh(gi_n + r * (ghn + bn));
            hreg = n + z * (hreg - n);
            outB[(size_t)t * (2 * HID) + gu] = hreg;
            if (s + 1 < SEQ) {
                const uint32_t dst = hb0 + (uint32_t)(((p ^ 1) * HID + gu) * 4);
                #pragma unroll
                for (int peer = 0; peer < SPLIT; peer++) {
                    uint32_t ra;
                    asm volatile("mapa.shared::cluster.u32 %0, %1, %2;"
                                 : "=r"(ra) : "r"(dst), "r"(peer));
                    asm volatile("st.shared::cluster.f32 [%0], %1;"
                                 :: "r"(ra), "f"(hreg) : "memory");
                }
            }
        }
        // orders DSMEM stores (release/acquire) + step lockstep
        asm volatile("barrier.cluster.arrive.aligned;" ::: "memory");
        asm volatile("barrier.cluster.wait.aligned;"   ::: "memory");
    }
}

// ----------------------------- sum dirs + LayerNorm ------------------------
__global__ void sum_ln_kernel(const float* __restrict__ in,
                              const float* __restrict__ gw,
                              const float* __restrict__ bw,
                              float* __restrict__ out)
{
    const int lane = threadIdx.x & 31;
    const size_t row = (size_t)blockIdx.x * 8 + (threadIdx.x >> 5);
    const float* r = in + row * 512;
    float v[8]; float s = 0.f, s2 = 0.f;
    #pragma unroll
    for (int i = 0; i < 8; i++) {
        int c = i * 32 + lane;
        v[i] = r[c] + r[256 + c];
        s += v[i]; s2 += v[i] * v[i];
    }
    #pragma unroll
    for (int off = 16; off; off >>= 1) {
        s  += __shfl_xor_sync(~0u, s,  off);
        s2 += __shfl_xor_sync(~0u, s2, off);
    }
    const float mu  = s * (1.f / 256.f);
    const float var = s2 * (1.f / 256.f) - mu * mu;
    const float inv = rsqrtf(var + 1e-5f);
    float* op = out + row * 256;
    #pragma unroll
    for (int i = 0; i < 8; i++) {
        int c = i * 32 + lane;
        op[c] = (v[i] - mu) * inv * gw[c] + bw[c];
    }
}

// ----------------------------- orchestration -------------------------------
extern "C" void kernel_launch(void* const* d_in, const int* in_sizes, int n_in,
                              void* d_out, int out_size)
{
    (void)in_sizes; (void)n_in; (void)out_size;
    const float* x      = (const float*)d_in[0];
    const float* w_ih0f = (const float*)d_in[1];
    const float* w_hh0f = (const float*)d_in[2];
    const float* b_ih0f = (const float*)d_in[3];
    const float* b_hh0f = (const float*)d_in[4];
    const float* w_ih0b = (const float*)d_in[5];
    const float* w_hh0b = (const float*)d_in[6];
    const float* b_ih0b = (const float*)d_in[7];
    const float* b_hh0b = (const float*)d_in[8];
    const float* w_ih1f = (const float*)d_in[9];
    const float* w_hh1f = (const float*)d_in[10];
    const float* b_ih1f = (const float*)d_in[11];
    const float* b_hh1f = (const float*)d_in[12];
    const float* w_ih1b = (const float*)d_in[13];
    const float* w_hh1b = (const float*)d_in[14];
    const float* b_ih1b = (const float*)d_in[15];
    const float* b_hh1b = (const float*)d_in[16];
    const float* ln_g   = (const float*)d_in[17];
    const float* ln_b   = (const float*)d_in[18];
    const float* w1     = (const float*)d_in[19];
    const float* b1     = (const float*)d_in[20];
    const float* w2     = (const float*)d_in[21];
    const float* b2     = (const float*)d_in[22];

    float *gi, *bufA, *bufB, *bufC;
    cudaGetSymbolAddress((void**)&gi,   g_gi);
    cudaGetSymbolAddress((void**)&bufA, g_bufA);
    cudaGetSymbolAddress((void**)&bufB, g_bufB);
    cudaGetSymbolAddress((void**)&bufC, g_bufC);

    const dim3 tb(32, 8);
    const dim3 gemm_grid(G3 / 128, M_ROWS / 128);

    transpose_k<<<dim3(SEQ / 32, CH / 32, BATCH), tb>>>(x, bufC, CH, SEQ);

    gemm_kernel<<<gemm_grid, 256>>>(bufC, w_ih0f, b_ih0f, gi,                       M_ROWS, G3, CH, 0);
    gemm_kernel<<<gemm_grid, 256>>>(bufC, w_ih0b, b_ih0b, gi + (size_t)M_ROWS * G3, M_ROWS, G3, CH, 0);

    scan_kernel<<<dim3(SPLIT, 2 * BATCH), STH>>>(gi, w_hh0f, b_hh0f, w_hh0b, b_hh0b, bufA);

    gemm_kernel<<<gemm_grid, 256>>>(bufA, w_ih1f, b_ih1f, gi,                       M_ROWS, G3, 2 * HID, 0);
    gemm_kernel<<<gemm_grid, 256>>>(bufA, w_ih1b, b_ih1b, gi + (size_t)M_ROWS * G3, M_ROWS, G3, 2 * HID, 0);

    scan_kernel<<<dim3(SPLIT, 2 * BATCH), STH>>>(gi, w_hh1f, b_hh1f, w_hh1b, b_hh1b, bufB);

    sum_ln_kernel<<<M_ROWS / 8, 256>>>(bufB, ln_g, ln_b, bufC);

    gemm_kernel<<<dim3(512 / 128, M_ROWS / 128), 256>>>(bufC, w1, b1, bufA, M_ROWS, 512, 256, 1);
    gemm_kernel<<<dim3(256 / 128, M_ROWS / 128), 256>>>(bufA, w2, b2, gi,   M_ROWS, 256, 512, 0);

    transpose_k<<<dim3(CH / 32, SEQ / 32, BATCH), tb>>>(gi, (float*)d_out, SEQ, CH);
}

// round 6
// speedup vs baseline: 1.4458x; 1.4347x over previous
#include <cuda_runtime.h>
#include <cstdint>

#define BATCH 16
#define CH    256
#define SEQ   2048
#define HID   256
#define G3    768
#define M_ROWS (BATCH*SEQ)

typedef unsigned long long ull;

__device__ __forceinline__ ull pack2(float x, float y) {
    ull r; asm("mov.b64 %0,{%1,%2};" : "=l"(r) : "f"(x), "f"(y)); return r;
}
__device__ __forceinline__ void unpack2(ull v, float& x, float& y) {
    asm("mov.b64 {%0,%1},%2;" : "=f"(x), "=f"(y) : "l"(v));
}
__device__ __forceinline__ ull fma2(ull a, ull b, ull c) {
    ull d; asm("fma.rn.f32x2 %0,%1,%2,%3;" : "=l"(d) : "l"(a), "l"(b), "l"(c)); return d;
}
__device__ __forceinline__ float fsig(float x) {
    return __fdividef(1.f, 1.f + __expf(-x));
}
__device__ __forceinline__ float ftanh(float x) {
    float t = __expf(-2.f * fabsf(x));
    return copysignf(__fdividef(1.f - t, 1.f + t), x);
}

__device__ float g_gi  [(size_t)2 * BATCH * SEQ * G3];
__device__ float g_bufA[(size_t)BATCH * SEQ * 2 * HID];
__device__ float g_bufB[(size_t)BATCH * SEQ * 2 * HID];
__device__ float g_bufC[(size_t)BATCH * SEQ * HID];

// ----------------------------- transpose -----------------------------------
__global__ void transpose_k(const float* __restrict__ src, float* __restrict__ dst,
                            int D1, int D2)
{
    __shared__ float tile[32][33];
    const int b  = blockIdx.z;
    const int j0 = blockIdx.x * 32;
    const int i0 = blockIdx.y * 32;
    const float* s = src + (size_t)b * D1 * D2;
    float*       d = dst + (size_t)b * D1 * D2;
    #pragma unroll
    for (int r = 0; r < 32; r += 8)
        tile[threadIdx.y + r][threadIdx.x] =
            s[(size_t)(i0 + threadIdx.y + r) * D2 + j0 + threadIdx.x];
    __syncthreads();
    #pragma unroll
    for (int r = 0; r < 32; r += 8)
        d[(size_t)(j0 + threadIdx.y + r) * D1 + i0 + threadIdx.x] =
            tile[threadIdx.x][threadIdx.y + r];
}

// ----------------------------- SGEMM (double-buffered) ---------------------
__global__ void __launch_bounds__(256, 2)
gemm_kernel(const float* __restrict__ A, const float* __restrict__ Bw,
            const float* __restrict__ bias, float* __restrict__ C,
            int M, int N, int K, int relu)
{
    __shared__ float As[2][16][128];
    __shared__ float Bs[2][16][128];
    const int tid = threadIdx.x;
    const int tx = tid & 15, ty = tid >> 4;
    const float* Ab = A  + (size_t)blockIdx.y * 128 * K;
    const float* Bb = Bw + (size_t)blockIdx.x * 128 * K;
    const int lrow = tid >> 1;
    const int lq   = (tid & 1) * 2;

    ull c2[8][4];
    #pragma unroll
    for (int i = 0; i < 8; i++)
        #pragma unroll
        for (int j = 0; j < 4; j++) c2[i][j] = 0ull;

    float4 ra0, ra1, rb0, rb1;
    {
        const float* ap = &Ab[(size_t)lrow * K + lq * 4];
        const float* bp = &Bb[(size_t)lrow * K + lq * 4];
        ra0 = *(const float4*)ap; ra1 = *(const float4*)(ap + 4);
        rb0 = *(const float4*)bp; rb1 = *(const float4*)(bp + 4);
    }
    {
        const int q = lq * 4;
        As[0][q+0][lrow]=ra0.x; As[0][q+1][lrow]=ra0.y; As[0][q+2][lrow]=ra0.z; As[0][q+3][lrow]=ra0.w;
        As[0][q+4][lrow]=ra1.x; As[0][q+5][lrow]=ra1.y; As[0][q+6][lrow]=ra1.z; As[0][q+7][lrow]=ra1.w;
        Bs[0][q+0][lrow]=rb0.x; Bs[0][q+1][lrow]=rb0.y; Bs[0][q+2][lrow]=rb0.z; Bs[0][q+3][lrow]=rb0.w;
        Bs[0][q+4][lrow]=rb1.x; Bs[0][q+5][lrow]=rb1.y; Bs[0][q+6][lrow]=rb1.z; Bs[0][q+7][lrow]=rb1.w;
    }
    __syncthreads();

    const int ktiles = K >> 4;
    int buf = 0;
    for (int it = 0; it < ktiles; it++) {
        const int more = (it + 1 < ktiles);
        if (more) {
            const int kt = (it + 1) * 16;
            const float* ap = &Ab[(size_t)lrow * K + kt + lq * 4];
            const float* bp = &Bb[(size_t)lrow * K + kt + lq * 4];
            ra0 = *(const float4*)ap; ra1 = *(const float4*)(ap + 4);
            rb0 = *(const float4*)bp; rb1 = *(const float4*)(bp + 4);
        }
        #pragma unroll
        for (int k = 0; k < 16; k++) {
            float4 a0 = *(const float4*)&As[buf][k][ty * 8];
            float4 a1 = *(const float4*)&As[buf][k][ty * 8 + 4];
            float4 b0 = *(const float4*)&Bs[buf][k][tx * 8];
            float4 b1 = *(const float4*)&Bs[buf][k][tx * 8 + 4];
            ull bp4[4] = { pack2(b0.x, b0.y), pack2(b0.z, b0.w),
                           pack2(b1.x, b1.y), pack2(b1.z, b1.w) };
            float av[8] = { a0.x, a0.y, a0.z, a0.w, a1.x, a1.y, a1.z, a1.w };
            #pragma unroll
            for (int i = 0; i < 8; i++) {
                ull as = pack2(av[i], av[i]);
                #pragma unroll
                for (int j = 0; j < 4; j++) c2[i][j] = fma2(as, bp4[j], c2[i][j]);
            }
        }
        if (more) {
            const int nb = buf ^ 1;
            const int q = lq * 4;
            As[nb][q+0][lrow]=ra0.x; As[nb][q+1][lrow]=ra0.y; As[nb][q+2][lrow]=ra0.z; As[nb][q+3][lrow]=ra0.w;
            As[nb][q+4][lrow]=ra1.x; As[nb][q+5][lrow]=ra1.y; As[nb][q+6][lrow]=ra1.z; As[nb][q+7][lrow]=ra1.w;
            Bs[nb][q+0][lrow]=rb0.x; Bs[nb][q+1][lrow]=rb0.y; Bs[nb][q+2][lrow]=rb0.z; Bs[nb][q+3][lrow]=rb0.w;
            Bs[nb][q+4][lrow]=rb1.x; Bs[nb][q+5][lrow]=rb1.y; Bs[nb][q+6][lrow]=rb1.z; Bs[nb][q+7][lrow]=rb1.w;
            __syncthreads();
            buf = nb;
        }
    }

    const int n0 = blockIdx.x * 128 + tx * 8;
    float bv[8];
    #pragma unroll
    for (int j = 0; j < 8; j++) bv[j] = bias[n0 + j];
    #pragma unroll
    for (int i = 0; i < 8; i++) {
        float o[8];
        #pragma unroll
        for (int j = 0; j < 4; j++) unpack2(c2[i][j], o[2*j], o[2*j+1]);
        #pragma unroll
        for (int j = 0; j < 8; j++) {
            o[j] += bv[j];
            if (relu) o[j] = fmaxf(o[j], 0.f);
        }
        float* cp = &C[((size_t)blockIdx.y * 128 + ty * 8 + i) * N + n0];
        *(float4*)cp       = make_float4(o[0], o[1], o[2], o[3]);
        *(float4*)(cp + 4) = make_float4(o[4], o[5], o[6], o[7]);
    }
}

// ----------------------------- GRU scan (R1 layout + ulonglong2 + fast math)
// Cluster of 4 CTAs per (batch,dir) chain. 384 threads: thread = (k-half g,
// gate row o). 64 f32x2 weights per thread (128 regs -- no spill). Dot reads
// h via LDS.128 as ulonglong2 (no mov.b64 packs). smem part[] reduce across
// the 2 k-halves; 64 gate threads do fast gate math, broadcast h_new to all
// 4 CTAs' next-parity buffer via st.shared::cluster; barrier.cluster syncs.
#define SPLIT 4
#define STH   384

__global__ void __launch_bounds__(STH, 1) __cluster_dims__(SPLIT, 1, 1)
scan_kernel(const float* __restrict__ gi,
            const float* __restrict__ whh_f, const float* __restrict__ bhh_f,
            const float* __restrict__ whh_b, const float* __restrict__ bhh_b,
            float* __restrict__ out)
{
    const int ci    = blockIdx.x;
    const int chain = blockIdx.y;
    const int b     = chain & (BATCH - 1);
    const int dir   = chain >> 4;
    const float* whh = dir ? whh_b : whh_f;
    const float* bhh = dir ? bhh_b : bhh_f;
    const float* giB = gi + ((size_t)dir * BATCH + b) * (size_t)SEQ * G3;
    float* outB = out + (size_t)b * SEQ * (2 * HID) + dir * HID;

    const int tid  = threadIdx.x;
    const int g    = tid / 192;          // k half
    const int o    = tid % 192;
    const int gate = o >> 6;
    const int jl   = o & 63;
    const int row  = gate * HID + ci * 64 + jl;
    const int gu   = ci * 64 + jl;

    __shared__ __align__(16) float hbuf[2][HID];
    __shared__ float part[STH];

    ull wreg[64];
    {
        const ull* wp = (const ull*)(whh + (size_t)row * HID + g * 128);
        #pragma unroll
        for (int i = 0; i < 64; i++) wreg[i] = wp[i];
    }
    const float bias = (g == 0) ? bhh[row] : 0.f;

    uint32_t hb0;
    asm("{ .reg .u64 t; cvta.to.shared.u64 t, %1; cvt.u32.u64 %0, t; }"
        : "=r"(hb0) : "l"(&hbuf[0][0]));

    for (int i = tid; i < 2 * HID; i += STH) (&hbuf[0][0])[i] = 0.f;
    __syncthreads();
    asm volatile("barrier.cluster.arrive.aligned;" ::: "memory");
    asm volatile("barrier.cluster.wait.aligned;"   ::: "memory");

    float hreg = 0.f;
    float p_r = 0.f, p_z = 0.f, p_n = 0.f;
    if (tid < 64) {
        const float* gp = giB + (size_t)(dir ? SEQ - 1 : 0) * G3 + gu;
        p_r = __ldg(gp); p_z = __ldg(gp + HID); p_n = __ldg(gp + 2 * HID);
    }

    for (int s = 0; s < SEQ; s++) {
        const int t = dir ? (SEQ - 1 - s) : s;
        const int p = s & 1;
        const float gi_r = p_r, gi_z = p_z, gi_n = p_n;
        if (tid < 64 && s + 1 < SEQ) {
            const int tn = dir ? (SEQ - 2 - s) : (s + 1);
            const float* gp = giB + (size_t)tn * G3 + gu;
            p_r = __ldg(gp); p_z = __ldg(gp + HID); p_n = __ldg(gp + 2 * HID);
        }

        // 128-long dot over this thread's k half; h read as 64-bit pairs
        ull acc0 = pack2(bias, 0.f);
        ull acc1 = 0ull;
        const ulonglong2* h2 = (const ulonglong2*)&hbuf[p][g * 128];
        #pragma unroll
        for (int kk = 0; kk < 32; kk++) {
            ulonglong2 hv = h2[kk];
            acc0 = fma2(wreg[2*kk],     hv.x, acc0);
            acc1 = fma2(wreg[2*kk + 1], hv.y, acc1);
        }
        float aa, bb, cc, dd;
        unpack2(acc0, aa, bb); unpack2(acc1, cc, dd);
        part[tid] = (aa + cc) + (bb + dd);
        __syncthreads();

        if (tid < 64) {
            const float gh_r = part[tid]       + part[192 + tid];
            const float gh_z = part[64 + tid]  + part[256 + tid];
            const float gh_n = part[128 + tid] + part[320 + tid];
            const float r = fsig(gi_r + gh_r);
            const float z = fsig(gi_z + gh_z);
            const float n = ftanh(gi_n + r * gh_n);
            hreg = n + z * (hreg - n);
            // DSMEM broadcast first (critical path), STG after
            const uint32_t dst = hb0 + (uint32_t)(((p ^ 1) * HID + gu) * 4);
            #pragma unroll
            for (int peer = 0; peer < SPLIT; peer++) {
                uint32_t ra;
                asm volatile("mapa.shared::cluster.u32 %0, %1, %2;"
                             : "=r"(ra) : "r"(dst), "r"(peer));
                asm volatile("st.shared::cluster.f32 [%0], %1;"
                             :: "r"(ra), "f"(hreg) : "memory");
            }
            outB[(size_t)t * (2 * HID) + gu] = hreg;
        }
        asm volatile("barrier.cluster.arrive.aligned;" ::: "memory");
        asm volatile("barrier.cluster.wait.aligned;"   ::: "memory");
    }
}

// ----------------------------- sum dirs + LayerNorm ------------------------
__global__ void sum_ln_kernel(const float* __restrict__ in,
                              const float* __restrict__ gw,
                              const float* __restrict__ bw,
                              float* __restrict__ out)
{
    const int lane = threadIdx.x & 31;
    const size_t row = (size_t)blockIdx.x * 8 + (threadIdx.x >> 5);
    const float* r = in + row * 512;
    float v[8]; float s = 0.f, s2 = 0.f;
    #pragma unroll
    for (int i = 0; i < 8; i++) {
        int c = i * 32 + lane;
        v[i] = r[c] + r[256 + c];
        s += v[i]; s2 += v[i] * v[i];
    }
    #pragma unroll
    for (int off = 16; off; off >>= 1) {
        s  += __shfl_xor_sync(~0u, s,  off);
        s2 += __shfl_xor_sync(~0u, s2, off);
    }
    const float mu  = s * (1.f / 256.f);
    const float var = s2 * (1.f / 256.f) - mu * mu;
    const float inv = rsqrtf(var + 1e-5f);
    float* op = out + row * 256;
    #pragma unroll
    for (int i = 0; i < 8; i++) {
        int c = i * 32 + lane;
        op[c] = (v[i] - mu) * inv * gw[c] + bw[c];
    }
}

// ----------------------------- orchestration -------------------------------
extern "C" void kernel_launch(void* const* d_in, const int* in_sizes, int n_in,
                              void* d_out, int out_size)
{
    (void)in_sizes; (void)n_in; (void)out_size;
    const float* x      = (const float*)d_in[0];
    const float* w_ih0f = (const float*)d_in[1];
    const float* w_hh0f = (const float*)d_in[2];
    const float* b_ih0f = (const float*)d_in[3];
    const float* b_hh0f = (const float*)d_in[4];
    const float* w_ih0b = (const float*)d_in[5];
    const float* w_hh0b = (const float*)d_in[6];
    const float* b_ih0b = (const float*)d_in[7];
    const float* b_hh0b = (const float*)d_in[8];
    const float* w_ih1f = (const float*)d_in[9];
    const float* w_hh1f = (const float*)d_in[10];
    const float* b_ih1f = (const float*)d_in[11];
    const float* b_hh1f = (const float*)d_in[12];
    const float* w_ih1b = (const float*)d_in[13];
    const float* w_hh1b = (const float*)d_in[14];
    const float* b_ih1b = (const float*)d_in[15];
    const float* b_hh1b = (const float*)d_in[16];
    const float* ln_g   = (const float*)d_in[17];
    const float* ln_b   = (const float*)d_in[18];
    const float* w1     = (const float*)d_in[19];
    const float* b1     = (const float*)d_in[20];
    const float* w2     = (const float*)d_in[21];
    const float* b2     = (const float*)d_in[22];

    float *gi, *bufA, *bufB, *bufC;
    cudaGetSymbolAddress((void**)&gi,   g_gi);
    cudaGetSymbolAddress((void**)&bufA, g_bufA);
    cudaGetSymbolAddress((void**)&bufB, g_bufB);
    cudaGetSymbolAddress((void**)&bufC, g_bufC);

    const dim3 tb(32, 8);
    const dim3 gemm_grid(G3 / 128, M_ROWS / 128);

    transpose_k<<<dim3(SEQ / 32, CH / 32, BATCH), tb>>>(x, bufC, CH, SEQ);

    gemm_kernel<<<gemm_grid, 256>>>(bufC, w_ih0f, b_ih0f, gi,                       M_ROWS, G3, CH, 0);
    gemm_kernel<<<gemm_grid, 256>>>(bufC, w_ih0b, b_ih0b, gi + (size_t)M_ROWS * G3, M_ROWS, G3, CH, 0);

    scan_kernel<<<dim3(SPLIT, 2 * BATCH), STH>>>(gi, w_hh0f, b_hh0f, w_hh0b, b_hh0b, bufA);

    gemm_kernel<<<gemm_grid, 256>>>(bufA, w_ih1f, b_ih1f, gi,                       M_ROWS, G3, 2 * HID, 0);
    gemm_kernel<<<gemm_grid, 256>>>(bufA, w_ih1b, b_ih1b, gi + (size_t)M_ROWS * G3, M_ROWS, G3, 2 * HID, 0);

    scan_kernel<<<dim3(SPLIT, 2 * BATCH), STH>>>(gi, w_hh1f, b_hh1f, w_hh1b, b_hh1b, bufB);

    sum_ln_kernel<<<M_ROWS / 8, 256>>>(bufB, ln_g, ln_b, bufC);

    gemm_kernel<<<dim3(512 / 128, M_ROWS / 128), 256>>>(bufC, w1, b1, bufA, M_ROWS, 512, 256, 1);
    gemm_kernel<<<dim3(256 / 128, M_ROWS / 128), 256>>>(bufA, w2, b2, gi,   M_ROWS, 256, 512, 0);

    transpose_k<<<dim3(CH / 32, SEQ / 32, BATCH), tb>>>(gi, (float*)d_out, SEQ, CH);
}